// round 9
// baseline (speedup 1.0000x reference)
#include <cuda_runtime.h>
#include <math.h>

// GATNET: N=20000, E=640000, IN=256, H=4, OUT=64
#define NN   20000
#define EE   640000
#define ET   (EE + NN)
#define KIN  256
#define HC   256
#define H1   4
#define C1   64
#define C2   64

__device__ float g_h1[NN * HC];
__device__ float g_x1[NN * HC];
__device__ float g_h2[NN * C2];
__device__ float g_as1[NN * H1];
__device__ float g_ad1[NN * H1];
__device__ float g_as2[NN];
__device__ float g_ad2[NN];
__device__ int   g_cnt[NN];
__device__ int   g_ptr[NN + 1];
__device__ int   g_cur[NN];
__device__ int   g_csr_src[ET];
__device__ float g_w1c[ET * H1];   // fallback only (cnt > 1024)
__device__ float g_w2c[ET];        // fallback only
__device__ int   g_is64;

// ---------------- dtype probe + zero counts (fused) ----------------
__global__ void detect_zero_k(const long long* __restrict__ ei64) {
    int t = blockIdx.x * blockDim.x + threadIdx.x;
    if (t < NN) g_cnt[t] = 0;
    if (blockIdx.x == 0) {
        __shared__ int bad;
        if (threadIdx.x == 0) bad = 0;
        __syncthreads();
        for (int i = threadIdx.x; i < 2048; i += blockDim.x) {
            long long v = ei64[i];
            if (v < 0 || v >= NN) bad = 1;
        }
        __syncthreads();
        if (threadIdx.x == 0) g_is64 = bad ? 0 : 1;
    }
}

__device__ __forceinline__ void load_edge(const void* __restrict__ ei, int e, int& s, int& d) {
    if (e >= EE) { s = d = e - EE; return; }
    if (g_is64) {
        const long long* p = (const long long*)ei;
        s = (int)p[e]; d = (int)p[EE + e];
    } else {
        const int* p = (const int*)ei;
        s = p[e]; d = p[EE + e];
    }
}

__global__ void count_k(const void* __restrict__ ei) {
    int e = blockIdx.x * blockDim.x + threadIdx.x;
    if (e >= ET) return;
    int s, d; load_edge(ei, e, s, d);
    if ((unsigned)d < NN) atomicAdd(&g_cnt[d], 1);
}

// ---------------- fast single-block scan: 20 elems/thread, warp-shuffle ----------------
__global__ __launch_bounds__(1024) void scan_fast_k() {
    const int T = 20;
    int tid = threadIdx.x;
    int base = tid * T;
    int pre[T];
    int s = 0;
#pragma unroll
    for (int i = 0; i < T; i++) {
        int idx = base + i;
        int v = (idx < NN) ? g_cnt[idx] : 0;
        pre[i] = s; s += v;
    }
    int lane = tid & 31, wid = tid >> 5;
    int incl = s;
#pragma unroll
    for (int o = 1; o < 32; o <<= 1) {
        int n = __shfl_up_sync(0xffffffffu, incl, o);
        if (lane >= o) incl += n;
    }
    __shared__ int wsum[32];
    if (lane == 31) wsum[wid] = incl;
    __syncthreads();
    if (wid == 0) {
        int v = wsum[lane];
        int wi = v;
#pragma unroll
        for (int o = 1; o < 32; o <<= 1) {
            int n = __shfl_up_sync(0xffffffffu, wi, o);
            if (lane >= o) wi += n;
        }
        wsum[lane] = wi - v;   // exclusive warp offset
    }
    __syncthreads();
    int off = wsum[wid] + incl - s;   // exclusive prefix of this thread
#pragma unroll
    for (int i = 0; i < T; i++) {
        int idx = base + i;
        if (idx < NN) { int p = off + pre[i]; g_ptr[idx] = p; g_cur[idx] = p; }
    }
    if (tid == 1023) g_ptr[NN] = off + s;
}

__global__ void scatter_k(const void* __restrict__ ei) {
    int e = blockIdx.x * blockDim.x + threadIdx.x;
    if (e >= ET) return;
    int s, d; load_edge(ei, e, s, d);
    if ((unsigned)d < NN && (unsigned)s < NN) {
        int pos = atomicAdd(&g_cur[d], 1);
        g_csr_src[pos] = s;
    }
}

// ---------------- SGEMM 128x128 tile, 8x8 microtile (for GEMM1, N%128==0) ----------------
__global__ __launch_bounds__(256) void sgemm128_k(const float* __restrict__ A,
                                                  const float* __restrict__ B,
                                                  float* __restrict__ C,
                                                  int M, int N, int K) {
    __shared__ float As[16][132];   // transposed: As[k][row]
    __shared__ float Bs[16][128];
    const int bm = blockIdx.y * 128;
    const int bn = blockIdx.x * 128;
    const int tid = threadIdx.x;
    const int tx = tid & 15;        // col group
    const int ty = tid >> 4;        // row group

    // load mapping: 512 float4 per tile, 2 per thread
    const int alin0 = tid * 2;
    const int blin0 = tid * 2;

    float4 aP[2], bP[2];
    // prefetch k0 = 0
#pragma unroll
    for (int i = 0; i < 2; i++) {
        int lin = alin0 + i;
        int row = lin >> 2, kc = lin & 3;
        int gm = bm + row;
        aP[i] = (gm < M) ? *(const float4*)&A[(size_t)gm * K + kc * 4]
                         : make_float4(0.f, 0.f, 0.f, 0.f);
        int lb = blin0 + i;
        int kr = lb >> 5, cc = lb & 31;
        bP[i] = *(const float4*)&B[(size_t)kr * N + bn + cc * 4];
    }

    float acc[8][8] = {};

    for (int k0 = 0; k0 < K; k0 += 16) {
        __syncthreads();
#pragma unroll
        for (int i = 0; i < 2; i++) {
            int lin = alin0 + i;
            int row = lin >> 2, kc = lin & 3;
            As[kc * 4 + 0][row] = aP[i].x;
            As[kc * 4 + 1][row] = aP[i].y;
            As[kc * 4 + 2][row] = aP[i].z;
            As[kc * 4 + 3][row] = aP[i].w;
            int lb = blin0 + i;
            int kr = lb >> 5, cc = lb & 31;
            *(float4*)&Bs[kr][cc * 4] = bP[i];
        }
        __syncthreads();
        // prefetch next tile
        if (k0 + 16 < K) {
#pragma unroll
            for (int i = 0; i < 2; i++) {
                int lin = alin0 + i;
                int row = lin >> 2, kc = lin & 3;
                int gm = bm + row;
                aP[i] = (gm < M) ? *(const float4*)&A[(size_t)gm * K + k0 + 16 + kc * 4]
                                 : make_float4(0.f, 0.f, 0.f, 0.f);
                int lb = blin0 + i;
                int kr = lb >> 5, cc = lb & 31;
                bP[i] = *(const float4*)&B[(size_t)(k0 + 16 + kr) * N + bn + cc * 4];
            }
        }
#pragma unroll
        for (int k = 0; k < 16; k++) {
            float4 a0 = *(const float4*)&As[k][ty * 4];
            float4 a1 = *(const float4*)&As[k][ty * 4 + 64];
            float4 b0 = *(const float4*)&Bs[k][tx * 4];
            float4 b1 = *(const float4*)&Bs[k][tx * 4 + 64];
            float av[8] = {a0.x, a0.y, a0.z, a0.w, a1.x, a1.y, a1.z, a1.w};
            float bv[8] = {b0.x, b0.y, b0.z, b0.w, b1.x, b1.y, b1.z, b1.w};
#pragma unroll
            for (int i = 0; i < 8; i++)
#pragma unroll
                for (int j = 0; j < 8; j++) acc[i][j] += av[i] * bv[j];
        }
    }

#pragma unroll
    for (int i = 0; i < 8; i++) {
        int gm = bm + ty * 4 + (i & 3) + (i >> 2) * 64;
        if (gm < M) {
            float* cp = &C[(size_t)gm * N + bn];
            *(float4*)&cp[tx * 4]      = make_float4(acc[i][0], acc[i][1], acc[i][2], acc[i][3]);
            *(float4*)&cp[tx * 4 + 64] = make_float4(acc[i][4], acc[i][5], acc[i][6], acc[i][7]);
        }
    }
}

// ---------------- SGEMM 64x64 tile (for GEMM2, N=64) ----------------
__global__ __launch_bounds__(256) void sgemm_k(const float* __restrict__ A,
                                               const float* __restrict__ B,
                                               float* __restrict__ C,
                                               int M, int N, int K) {
    __shared__ float As[16][68];
    __shared__ float Bs[16][64];
    const int bn = blockIdx.x * 64;
    const int bm = blockIdx.y * 64;
    const int tid = threadIdx.x;
    const int tx = tid & 15, ty = tid >> 4;
    const int la_k = tid & 15, la_m = tid >> 4;
    const int lb_c = tid & 63, lb_k = tid >> 6;
    float acc[4][4] = {};

    for (int k0 = 0; k0 < K; k0 += 16) {
#pragma unroll
        for (int i = 0; i < 4; i++) {
            int m = la_m + i * 16;
            int gm = bm + m;
            As[la_k][m] = (gm < M) ? A[(size_t)gm * K + k0 + la_k] : 0.0f;
        }
#pragma unroll
        for (int i = 0; i < 4; i++) {
            int kk = lb_k + i * 4;
            Bs[kk][lb_c] = B[(size_t)(k0 + kk) * N + bn + lb_c];
        }
        __syncthreads();
#pragma unroll
        for (int k = 0; k < 16; k++) {
            float4 a4 = *(const float4*)&As[k][ty * 4];
            float4 b4 = *(const float4*)&Bs[k][tx * 4];
            float av[4] = {a4.x, a4.y, a4.z, a4.w};
            float bv[4] = {b4.x, b4.y, b4.z, b4.w};
#pragma unroll
            for (int i = 0; i < 4; i++)
#pragma unroll
                for (int j = 0; j < 4; j++) acc[i][j] += av[i] * bv[j];
        }
        __syncthreads();
    }
#pragma unroll
    for (int i = 0; i < 4; i++) {
        int gm = bm + ty * 4 + i;
        if (gm < M)
#pragma unroll
            for (int j = 0; j < 4; j++)
                C[(size_t)gm * N + bn + tx * 4 + j] = acc[i][j];
    }
}

// ---------------- attention logits ----------------
__global__ void att1_k(const float* __restrict__ att_src, const float* __restrict__ att_dst) {
    int t = blockIdx.x * blockDim.x + threadIdx.x;
    if (t >= NN * H1) return;
    int n = t / H1, h = t % H1;
    const float* row = g_h1 + (size_t)n * HC + h * C1;
    const float* asv = att_src + h * C1;
    const float* adv = att_dst + h * C1;
    float s = 0.f, d = 0.f;
#pragma unroll 8
    for (int c = 0; c < C1; c++) { float v = row[c]; s += v * asv[c]; d += v * adv[c]; }
    g_as1[t] = s; g_ad1[t] = d;
}

__global__ void att2_k(const float* __restrict__ att_src, const float* __restrict__ att_dst) {
    int n = blockIdx.x * blockDim.x + threadIdx.x;
    if (n >= NN) return;
    const float* row = g_h2 + (size_t)n * C2;
    float s = 0.f, d = 0.f;
#pragma unroll 8
    for (int c = 0; c < C2; c++) { float v = row[c]; s += v * att_src[c]; d += v * att_dst[c]; }
    g_as2[n] = s; g_ad2[n] = d;
}

// ---------------- fused edge-softmax + gather, layer 1 ----------------
#define SM1 1024
__global__ __launch_bounds__(256) void gat1_k(const float* __restrict__ bias1) {
    __shared__ float wsh[SM1 * H1];   // 16 KB
    const int d = blockIdx.x;
    const int tid = threadIdx.x;
    const int p0 = g_ptr[d], p1 = g_ptr[d + 1];
    const int cnt = p1 - p0;
    const bool inSm = (cnt <= SM1);

    float loc[H1] = {0.f, 0.f, 0.f, 0.f};
    const int items = cnt * H1;
    for (int i = tid; i < items; i += 256) {
        int j = p0 + (i >> 2);
        int h = i & 3;
        int s = g_csr_src[j];
        float x = g_as1[s * H1 + h] + g_ad1[d * H1 + h];
        x = (x > 0.f) ? x : 0.2f * x;
        x = fmaxf(x, -60.f);
        float w = expf(x);
        if (inSm) wsh[(j - p0) * H1 + h] = w;
        else      g_w1c[j * H1 + h] = w;
        loc[h] += w;
    }
#pragma unroll
    for (int h = 0; h < H1; h++)
#pragma unroll
        for (int o = 16; o; o >>= 1) loc[h] += __shfl_down_sync(0xffffffffu, loc[h], o);
    __shared__ float sw[8][H1];
    if ((tid & 31) == 0)
#pragma unroll
        for (int h = 0; h < H1; h++) sw[tid >> 5][h] = loc[h];
    __syncthreads();
    __shared__ float sinv[H1];
    if (tid < H1) {
        float s = 0.f;
#pragma unroll
        for (int w = 0; w < 8; w++) s += sw[w][tid];
        sinv[tid] = 1.0f / (s + 1e-16f);
    }
    __syncthreads();

    const int f = tid, h = f >> 6;
    const float inv = sinv[h];
    float acc = 0.f;
    if (inSm) {
        for (int j = p0; j < p1; j++) {
            int s = g_csr_src[j];
            acc += wsh[(j - p0) * H1 + h] * g_h1[(size_t)s * HC + f];
        }
    } else {
        for (int j = p0; j < p1; j++) {
            int s = g_csr_src[j];
            acc += g_w1c[j * H1 + h] * g_h1[(size_t)s * HC + f];
        }
    }
    float v = acc * inv + bias1[f];
    g_x1[(size_t)d * HC + f] = (v > 0.f) ? v : expm1f(v);   // ELU
}

// ---------------- fused edge-softmax + gather, layer 2 ----------------
#define SM2 2048
__global__ __launch_bounds__(64) void gat2_k(const float* __restrict__ bias2,
                                             float* __restrict__ out) {
    __shared__ float wsh[SM2];   // 8 KB
    const int d = blockIdx.x;
    const int tid = threadIdx.x;
    const int p0 = g_ptr[d], p1 = g_ptr[d + 1];
    const int cnt = p1 - p0;
    const bool inSm = (cnt <= SM2);

    float loc = 0.f;
    const float ad = g_ad2[d];
    for (int i = tid; i < cnt; i += 64) {
        int j = p0 + i;
        int s = g_csr_src[j];
        float x = g_as2[s] + ad;
        x = (x > 0.f) ? x : 0.2f * x;
        x = fmaxf(x, -60.f);
        float w = expf(x);
        if (inSm) wsh[i] = w;
        else      g_w2c[j] = w;
        loc += w;
    }
#pragma unroll
    for (int o = 16; o; o >>= 1) loc += __shfl_down_sync(0xffffffffu, loc, o);
    __shared__ float sw2[2];
    if ((tid & 31) == 0) sw2[tid >> 5] = loc;
    __syncthreads();
    __shared__ float sinv2;
    if (tid == 0) sinv2 = 1.0f / (sw2[0] + sw2[1] + 1e-16f);
    __syncthreads();

    const int f = tid;
    const float inv = sinv2;
    float acc = 0.f;
    if (inSm) {
        for (int j = p0; j < p1; j++) {
            int s = g_csr_src[j];
            acc += wsh[j - p0] * g_h2[(size_t)s * C2 + f];
        }
    } else {
        for (int j = p0; j < p1; j++) {
            int s = g_csr_src[j];
            acc += g_w2c[j] * g_h2[(size_t)s * C2 + f];
        }
    }
    out[(size_t)d * C2 + f] = acc * inv + bias2[f];
}

// ---------------- launch ----------------
extern "C" void kernel_launch(void* const* d_in, const int* in_sizes, int n_in,
                              void* d_out, int out_size) {
    const float* x   = (const float*)d_in[0];
    const void*  ei  = d_in[1];
    const float* W1  = (const float*)d_in[2];
    const float* as1 = (const float*)d_in[3];
    const float* ad1 = (const float*)d_in[4];
    const float* b1  = (const float*)d_in[5];
    const float* W2  = (const float*)d_in[6];
    const float* as2 = (const float*)d_in[7];
    const float* ad2 = (const float*)d_in[8];
    const float* b2  = (const float*)d_in[9];
    float* out = (float*)d_out;

    // R7 root cause: must resolve true device addresses of __device__ symbols
    // for use as kernel arguments (host shadow writes are silently absorbed by ATS).
    float *h1p = nullptr, *x1p = nullptr, *h2p = nullptr;
    cudaGetSymbolAddress((void**)&h1p, g_h1);
    cudaGetSymbolAddress((void**)&x1p, g_x1);
    cudaGetSymbolAddress((void**)&h2p, g_h2);

    detect_zero_k<<<(NN + 255) / 256, 256>>>((const long long*)ei);
    count_k<<<(ET + 255) / 256, 256>>>(ei);
    scan_fast_k<<<1, 1024>>>();
    scatter_k<<<(ET + 255) / 256, 256>>>(ei);

    // layer 1: h1 = x @ W1  (20000x256 @ 256x256)
    { dim3 g(HC / 128, (NN + 127) / 128); sgemm128_k<<<g, 256>>>(x, W1, h1p, NN, HC, KIN); }
    att1_k<<<(NN * H1 + 255) / 256, 256>>>(as1, ad1);
    gat1_k<<<NN, 256>>>(b1);

    // layer 2: h2 = x1 @ W2  (20000x256 @ 256x64)
    { dim3 g(C2 / 64, (NN + 63) / 64); sgemm_k<<<g, 256>>>(x1p, W2, h2p, NN, C2, HC); }
    att2_k<<<(NN + 255) / 256, 256>>>(as2, ad2);
    gat2_k<<<NN, 64>>>(b2, out);
}

// round 10
// speedup vs baseline: 1.0427x; 1.0427x over previous
#include <cuda_runtime.h>
#include <math.h>

// GATNET: N=20000, E=640000, IN=256, H=4, OUT=64
#define NN   20000
#define EE   640000
#define ET   (EE + NN)
#define KIN  256
#define HC   256
#define H1   4
#define C1   64
#define C2   64

__device__ float g_h1[NN * HC];
__device__ float g_x1[NN * HC];
__device__ float g_h2[NN * C2];
__device__ float g_as1[NN * H1];
__device__ float g_ad1[NN * H1];
__device__ float g_as2[NN];
__device__ float g_ad2[NN];
__device__ int   g_cnt[NN];
__device__ int   g_ptr[NN + 1];
__device__ int   g_cur[NN];
__device__ int   g_csr_src[ET];
__device__ float g_w1c[ET * H1];   // fallback only (cnt > 1024)
__device__ float g_w2c[ET];        // fallback only
__device__ int   g_is64;

// ---------------- dtype probe + zero counts (fused) ----------------
__global__ void detect_zero_k(const long long* __restrict__ ei64) {
    int t = blockIdx.x * blockDim.x + threadIdx.x;
    if (t < NN) g_cnt[t] = 0;
    if (blockIdx.x == 0) {
        __shared__ int bad;
        if (threadIdx.x == 0) bad = 0;
        __syncthreads();
        for (int i = threadIdx.x; i < 2048; i += blockDim.x) {
            long long v = ei64[i];
            if (v < 0 || v >= NN) bad = 1;
        }
        __syncthreads();
        if (threadIdx.x == 0) g_is64 = bad ? 0 : 1;
    }
}

__device__ __forceinline__ void load_edge(const void* __restrict__ ei, int e, int& s, int& d) {
    if (e >= EE) { s = d = e - EE; return; }
    if (g_is64) {
        const long long* p = (const long long*)ei;
        s = (int)p[e]; d = (int)p[EE + e];
    } else {
        const int* p = (const int*)ei;
        s = p[e]; d = p[EE + e];
    }
}

__global__ void count_k(const void* __restrict__ ei) {
    int e = blockIdx.x * blockDim.x + threadIdx.x;
    if (e >= ET) return;
    int s, d; load_edge(ei, e, s, d);
    if ((unsigned)d < NN) atomicAdd(&g_cnt[d], 1);
}

// ---------------- fast single-block scan: 20 elems/thread, warp-shuffle ----------------
__global__ __launch_bounds__(1024) void scan_fast_k() {
    const int T = 20;
    int tid = threadIdx.x;
    int base = tid * T;
    int pre[T];
    int s = 0;
#pragma unroll
    for (int i = 0; i < T; i++) {
        int idx = base + i;
        int v = (idx < NN) ? g_cnt[idx] : 0;
        pre[i] = s; s += v;
    }
    int lane = tid & 31, wid = tid >> 5;
    int incl = s;
#pragma unroll
    for (int o = 1; o < 32; o <<= 1) {
        int n = __shfl_up_sync(0xffffffffu, incl, o);
        if (lane >= o) incl += n;
    }
    __shared__ int wsum[32];
    if (lane == 31) wsum[wid] = incl;
    __syncthreads();
    if (wid == 0) {
        int v = wsum[lane];
        int wi = v;
#pragma unroll
        for (int o = 1; o < 32; o <<= 1) {
            int n = __shfl_up_sync(0xffffffffu, wi, o);
            if (lane >= o) wi += n;
        }
        wsum[lane] = wi - v;   // exclusive warp offset
    }
    __syncthreads();
    int off = wsum[wid] + incl - s;   // exclusive prefix of this thread
#pragma unroll
    for (int i = 0; i < T; i++) {
        int idx = base + i;
        if (idx < NN) { int p = off + pre[i]; g_ptr[idx] = p; g_cur[idx] = p; }
    }
    if (tid == 1023) g_ptr[NN] = off + s;
}

__global__ void scatter_k(const void* __restrict__ ei) {
    int e = blockIdx.x * blockDim.x + threadIdx.x;
    if (e >= ET) return;
    int s, d; load_edge(ei, e, s, d);
    if ((unsigned)d < NN && (unsigned)s < NN) {
        int pos = atomicAdd(&g_cur[d], 1);
        g_csr_src[pos] = s;
    }
}

// ---------------- SGEMM 64x64 tile (proven: good wave balance at this size) ----------------
__global__ __launch_bounds__(256) void sgemm_k(const float* __restrict__ A,
                                               const float* __restrict__ B,
                                               float* __restrict__ C,
                                               int M, int N, int K) {
    __shared__ float As[16][68];
    __shared__ float Bs[16][64];
    const int bn = blockIdx.x * 64;
    const int bm = blockIdx.y * 64;
    const int tid = threadIdx.x;
    const int tx = tid & 15, ty = tid >> 4;
    const int la_k = tid & 15, la_m = tid >> 4;
    const int lb_c = tid & 63, lb_k = tid >> 6;
    float acc[4][4] = {};

    for (int k0 = 0; k0 < K; k0 += 16) {
#pragma unroll
        for (int i = 0; i < 4; i++) {
            int m = la_m + i * 16;
            int gm = bm + m;
            As[la_k][m] = (gm < M) ? A[(size_t)gm * K + k0 + la_k] : 0.0f;
        }
#pragma unroll
        for (int i = 0; i < 4; i++) {
            int kk = lb_k + i * 4;
            Bs[kk][lb_c] = B[(size_t)(k0 + kk) * N + bn + lb_c];
        }
        __syncthreads();
#pragma unroll
        for (int k = 0; k < 16; k++) {
            float4 a4 = *(const float4*)&As[k][ty * 4];
            float4 b4 = *(const float4*)&Bs[k][tx * 4];
            float av[4] = {a4.x, a4.y, a4.z, a4.w};
            float bv[4] = {b4.x, b4.y, b4.z, b4.w};
#pragma unroll
            for (int i = 0; i < 4; i++)
#pragma unroll
                for (int j = 0; j < 4; j++) acc[i][j] += av[i] * bv[j];
        }
        __syncthreads();
    }
#pragma unroll
    for (int i = 0; i < 4; i++) {
        int gm = bm + ty * 4 + i;
        if (gm < M)
#pragma unroll
            for (int j = 0; j < 4; j++)
                C[(size_t)gm * N + bn + tx * 4 + j] = acc[i][j];
    }
}

// ---------------- attention logits ----------------
__global__ void att1_k(const float* __restrict__ att_src, const float* __restrict__ att_dst) {
    int t = blockIdx.x * blockDim.x + threadIdx.x;
    if (t >= NN * H1) return;
    int n = t / H1, h = t % H1;
    const float* row = g_h1 + (size_t)n * HC + h * C1;
    const float* asv = att_src + h * C1;
    const float* adv = att_dst + h * C1;
    float s = 0.f, d = 0.f;
#pragma unroll 8
    for (int c = 0; c < C1; c++) { float v = row[c]; s += v * asv[c]; d += v * adv[c]; }
    g_as1[t] = s; g_ad1[t] = d;
}

__global__ void att2_k(const float* __restrict__ att_src, const float* __restrict__ att_dst) {
    int n = blockIdx.x * blockDim.x + threadIdx.x;
    if (n >= NN) return;
    const float* row = g_h2 + (size_t)n * C2;
    float s = 0.f, d = 0.f;
#pragma unroll 8
    for (int c = 0; c < C2; c++) { float v = row[c]; s += v * att_src[c]; d += v * att_dst[c]; }
    g_as2[n] = s; g_ad2[n] = d;
}

// ---------------- fused edge-softmax + gather, layer 1 ----------------
#define SM1 1024
__global__ __launch_bounds__(256) void gat1_k(const float* __restrict__ bias1) {
    __shared__ float wsh[SM1 * H1];   // 16 KB
    const int d = blockIdx.x;
    const int tid = threadIdx.x;
    const int p0 = g_ptr[d], p1 = g_ptr[d + 1];
    const int cnt = p1 - p0;
    const bool inSm = (cnt <= SM1);

    float loc[H1] = {0.f, 0.f, 0.f, 0.f};
    const int items = cnt * H1;
    for (int i = tid; i < items; i += 256) {
        int j = p0 + (i >> 2);
        int h = i & 3;
        int s = g_csr_src[j];
        float x = g_as1[s * H1 + h] + g_ad1[d * H1 + h];
        x = (x > 0.f) ? x : 0.2f * x;
        x = fmaxf(x, -60.f);
        float w = expf(x);
        if (inSm) wsh[(j - p0) * H1 + h] = w;
        else      g_w1c[j * H1 + h] = w;
        loc[h] += w;
    }
#pragma unroll
    for (int h = 0; h < H1; h++)
#pragma unroll
        for (int o = 16; o; o >>= 1) loc[h] += __shfl_down_sync(0xffffffffu, loc[h], o);
    __shared__ float sw[8][H1];
    if ((tid & 31) == 0)
#pragma unroll
        for (int h = 0; h < H1; h++) sw[tid >> 5][h] = loc[h];
    __syncthreads();
    __shared__ float sinv[H1];
    if (tid < H1) {
        float s = 0.f;
#pragma unroll
        for (int w = 0; w < 8; w++) s += sw[w][tid];
        sinv[tid] = 1.0f / (s + 1e-16f);
    }
    __syncthreads();

    const int f = tid, h = f >> 6;
    const float inv = sinv[h];
    float acc = 0.f;
    if (inSm) {
        for (int j = p0; j < p1; j++) {
            int s = g_csr_src[j];
            acc += wsh[(j - p0) * H1 + h] * g_h1[(size_t)s * HC + f];
        }
    } else {
        for (int j = p0; j < p1; j++) {
            int s = g_csr_src[j];
            acc += g_w1c[j * H1 + h] * g_h1[(size_t)s * HC + f];
        }
    }
    float v = acc * inv + bias1[f];
    g_x1[(size_t)d * HC + f] = (v > 0.f) ? v : expm1f(v);   // ELU
}

// ---------------- fused edge-softmax + gather, layer 2 ----------------
#define SM2 2048
__global__ __launch_bounds__(64) void gat2_k(const float* __restrict__ bias2,
                                             float* __restrict__ out) {
    __shared__ float wsh[SM2];   // 8 KB
    const int d = blockIdx.x;
    const int tid = threadIdx.x;
    const int p0 = g_ptr[d], p1 = g_ptr[d + 1];
    const int cnt = p1 - p0;
    const bool inSm = (cnt <= SM2);

    float loc = 0.f;
    const float ad = g_ad2[d];
    for (int i = tid; i < cnt; i += 64) {
        int j = p0 + i;
        int s = g_csr_src[j];
        float x = g_as2[s] + ad;
        x = (x > 0.f) ? x : 0.2f * x;
        x = fmaxf(x, -60.f);
        float w = expf(x);
        if (inSm) wsh[i] = w;
        else      g_w2c[j] = w;
        loc += w;
    }
#pragma unroll
    for (int o = 16; o; o >>= 1) loc += __shfl_down_sync(0xffffffffu, loc, o);
    __shared__ float sw2[2];
    if ((tid & 31) == 0) sw2[tid >> 5] = loc;
    __syncthreads();
    __shared__ float sinv2;
    if (tid == 0) sinv2 = 1.0f / (sw2[0] + sw2[1] + 1e-16f);
    __syncthreads();

    const int f = tid;
    const float inv = sinv2;
    float acc = 0.f;
    if (inSm) {
        for (int j = p0; j < p1; j++) {
            int s = g_csr_src[j];
            acc += wsh[j - p0] * g_h2[(size_t)s * C2 + f];
        }
    } else {
        for (int j = p0; j < p1; j++) {
            int s = g_csr_src[j];
            acc += g_w2c[j] * g_h2[(size_t)s * C2 + f];
        }
    }
    out[(size_t)d * C2 + f] = acc * inv + bias2[f];
}

// ---------------- launch ----------------
extern "C" void kernel_launch(void* const* d_in, const int* in_sizes, int n_in,
                              void* d_out, int out_size) {
    const float* x   = (const float*)d_in[0];
    const void*  ei  = d_in[1];
    const float* W1  = (const float*)d_in[2];
    const float* as1 = (const float*)d_in[3];
    const float* ad1 = (const float*)d_in[4];
    const float* b1  = (const float*)d_in[5];
    const float* W2  = (const float*)d_in[6];
    const float* as2 = (const float*)d_in[7];
    const float* ad2 = (const float*)d_in[8];
    const float* b2  = (const float*)d_in[9];
    float* out = (float*)d_out;

    // R7 root cause: resolve true device addresses of __device__ symbols for
    // use as kernel arguments (host-shadow writes are silently absorbed by ATS).
    float *h1p = nullptr, *x1p = nullptr, *h2p = nullptr;
    cudaGetSymbolAddress((void**)&h1p, g_h1);
    cudaGetSymbolAddress((void**)&x1p, g_x1);
    cudaGetSymbolAddress((void**)&h2p, g_h2);

    detect_zero_k<<<(NN + 255) / 256, 256>>>((const long long*)ei);
    count_k<<<(ET + 255) / 256, 256>>>(ei);
    scan_fast_k<<<1, 1024>>>();
    scatter_k<<<(ET + 255) / 256, 256>>>(ei);

    // layer 1: h1 = x @ W1  (20000x256 @ 256x256)
    { dim3 g(HC / 64, (NN + 63) / 64); sgemm_k<<<g, 256>>>(x, W1, h1p, NN, HC, KIN); }
    att1_k<<<(NN * H1 + 255) / 256, 256>>>(as1, ad1);
    gat1_k<<<NN, 256>>>(b1);

    // layer 2: h2 = x1 @ W2  (20000x256 @ 256x64)
    { dim3 g(C2 / 64, (NN + 63) / 64); sgemm_k<<<g, 256>>>(x1p, W2, h2p, NN, C2, HC); }
    att2_k<<<(NN + 255) / 256, 256>>>(as2, ad2);
    gat2_k<<<NN, 64>>>(b2, out);
}

// round 11
// speedup vs baseline: 1.1448x; 1.0979x over previous
#include <cuda_runtime.h>
#include <cuda_fp16.h>
#include <math.h>

// GATNET: N=20000, E=640000, IN=256, H=4, OUT=64
#define NN   20000
#define EE   640000
#define ET   (EE + NN)
#define KIN  256
#define HC   256
#define H1   4
#define C1   64
#define C2   64

__device__ float  g_h1[NN * HC];
__device__ __half g_h1h[NN * HC];   // fp16 copy for the edge gather
__device__ float  g_x1[NN * HC];
__device__ float  g_h2[NN * C2];
__device__ __half g_h2h[NN * C2];
__device__ float  g_as1[NN * H1];
__device__ float  g_ad1[NN * H1];
__device__ float  g_as2[NN];
__device__ float  g_ad2[NN];
__device__ int    g_cnt[NN];
__device__ int    g_ptr[NN + 1];
__device__ int    g_cur[NN];
__device__ int    g_csr_src[ET];
__device__ float  g_w1c[ET * H1];
__device__ float  g_w2c[ET];
__device__ int    g_is64;

// ---------------- dtype probe + zero counts (fused) ----------------
__global__ void detect_zero_k(const long long* __restrict__ ei64) {
    int t = blockIdx.x * blockDim.x + threadIdx.x;
    if (t < NN) g_cnt[t] = 0;
    if (blockIdx.x == 0) {
        __shared__ int bad;
        if (threadIdx.x == 0) bad = 0;
        __syncthreads();
        for (int i = threadIdx.x; i < 2048; i += blockDim.x) {
            long long v = ei64[i];
            if (v < 0 || v >= NN) bad = 1;
        }
        __syncthreads();
        if (threadIdx.x == 0) g_is64 = bad ? 0 : 1;
    }
}

__device__ __forceinline__ void load_edge(const void* __restrict__ ei, int e, int& s, int& d) {
    if (e >= EE) { s = d = e - EE; return; }
    if (g_is64) {
        const long long* p = (const long long*)ei;
        s = (int)p[e]; d = (int)p[EE + e];
    } else {
        const int* p = (const int*)ei;
        s = p[e]; d = p[EE + e];
    }
}

__global__ void count_k(const void* __restrict__ ei) {
    int e = blockIdx.x * blockDim.x + threadIdx.x;
    if (e >= ET) return;
    int s, d; load_edge(ei, e, s, d);
    if ((unsigned)d < NN) atomicAdd(&g_cnt[d], 1);
}

// ---------------- fast single-block scan ----------------
__global__ __launch_bounds__(1024) void scan_fast_k() {
    const int T = 20;
    int tid = threadIdx.x;
    int base = tid * T;
    int pre[T];
    int s = 0;
#pragma unroll
    for (int i = 0; i < T; i++) {
        int idx = base + i;
        int v = (idx < NN) ? g_cnt[idx] : 0;
        pre[i] = s; s += v;
    }
    int lane = tid & 31, wid = tid >> 5;
    int incl = s;
#pragma unroll
    for (int o = 1; o < 32; o <<= 1) {
        int n = __shfl_up_sync(0xffffffffu, incl, o);
        if (lane >= o) incl += n;
    }
    __shared__ int wsum[32];
    if (lane == 31) wsum[wid] = incl;
    __syncthreads();
    if (wid == 0) {
        int v = wsum[lane];
        int wi = v;
#pragma unroll
        for (int o = 1; o < 32; o <<= 1) {
            int n = __shfl_up_sync(0xffffffffu, wi, o);
            if (lane >= o) wi += n;
        }
        wsum[lane] = wi - v;
    }
    __syncthreads();
    int off = wsum[wid] + incl - s;
#pragma unroll
    for (int i = 0; i < T; i++) {
        int idx = base + i;
        if (idx < NN) { int p = off + pre[i]; g_ptr[idx] = p; g_cur[idx] = p; }
    }
    if (tid == 1023) g_ptr[NN] = off + s;
}

__global__ void scatter_k(const void* __restrict__ ei) {
    int e = blockIdx.x * blockDim.x + threadIdx.x;
    if (e >= ET) return;
    int s, d; load_edge(ei, e, s, d);
    if ((unsigned)d < NN && (unsigned)s < NN) {
        int pos = atomicAdd(&g_cur[d], 1);
        g_csr_src[pos] = s;
    }
}

// ---------------- SGEMM 64x64 tile; fp32 out + fp16 copy ----------------
__global__ __launch_bounds__(256) void sgemm_k(const float* __restrict__ A,
                                               const float* __restrict__ B,
                                               float* __restrict__ C,
                                               __half* __restrict__ Ch,
                                               int M, int N, int K) {
    __shared__ float As[16][68];
    __shared__ float Bs[16][64];
    const int bn = blockIdx.x * 64;
    const int bm = blockIdx.y * 64;
    const int tid = threadIdx.x;
    const int tx = tid & 15, ty = tid >> 4;
    const int la_k = tid & 15, la_m = tid >> 4;
    const int lb_c = tid & 63, lb_k = tid >> 6;
    float acc[4][4] = {};

    for (int k0 = 0; k0 < K; k0 += 16) {
#pragma unroll
        for (int i = 0; i < 4; i++) {
            int m = la_m + i * 16;
            int gm = bm + m;
            As[la_k][m] = (gm < M) ? A[(size_t)gm * K + k0 + la_k] : 0.0f;
        }
#pragma unroll
        for (int i = 0; i < 4; i++) {
            int kk = lb_k + i * 4;
            Bs[kk][lb_c] = B[(size_t)(k0 + kk) * N + bn + lb_c];
        }
        __syncthreads();
#pragma unroll
        for (int k = 0; k < 16; k++) {
            float4 a4 = *(const float4*)&As[k][ty * 4];
            float4 b4 = *(const float4*)&Bs[k][tx * 4];
            float av[4] = {a4.x, a4.y, a4.z, a4.w};
            float bv[4] = {b4.x, b4.y, b4.z, b4.w};
#pragma unroll
            for (int i = 0; i < 4; i++)
#pragma unroll
                for (int j = 0; j < 4; j++) acc[i][j] += av[i] * bv[j];
        }
        __syncthreads();
    }
#pragma unroll
    for (int i = 0; i < 4; i++) {
        int gm = bm + ty * 4 + i;
        if (gm < M) {
            float* cp = &C[(size_t)gm * N + bn + tx * 4];
            *(float4*)cp = make_float4(acc[i][0], acc[i][1], acc[i][2], acc[i][3]);
            __half2* hp = (__half2*)&Ch[(size_t)gm * N + bn + tx * 4];
            hp[0] = __floats2half2_rn(acc[i][0], acc[i][1]);
            hp[1] = __floats2half2_rn(acc[i][2], acc[i][3]);
        }
    }
}

// ---------------- attention logits ----------------
__global__ void att1_k(const float* __restrict__ att_src, const float* __restrict__ att_dst) {
    int t = blockIdx.x * blockDim.x + threadIdx.x;
    if (t >= NN * H1) return;
    int n = t / H1, h = t % H1;
    const float* row = g_h1 + (size_t)n * HC + h * C1;
    const float* asv = att_src + h * C1;
    const float* adv = att_dst + h * C1;
    float s = 0.f, d = 0.f;
#pragma unroll 8
    for (int c = 0; c < C1; c++) { float v = row[c]; s += v * asv[c]; d += v * adv[c]; }
    g_as1[t] = s; g_ad1[t] = d;
}

__global__ void att2_k(const float* __restrict__ att_src, const float* __restrict__ att_dst) {
    int n = blockIdx.x * blockDim.x + threadIdx.x;
    if (n >= NN) return;
    const float* row = g_h2 + (size_t)n * C2;
    float s = 0.f, d = 0.f;
#pragma unroll 8
    for (int c = 0; c < C2; c++) { float v = row[c]; s += v * att_src[c]; d += v * att_dst[c]; }
    g_as2[n] = s; g_ad2[n] = d;
}

// ---------------- fused edge-softmax + fp16 gather, layer 1 ----------------
__global__ __launch_bounds__(256) void gat1_k(const float* __restrict__ bias1) {
    const int d = blockIdx.x;
    const int tid = threadIdx.x;
    const int p0 = g_ptr[d], p1 = g_ptr[d + 1];
    const int cnt = p1 - p0;

    // pass 1: weights + denominator (fp32, exact)
    float loc[H1] = {0.f, 0.f, 0.f, 0.f};
    const int items = cnt * H1;
    for (int i = tid; i < items; i += 256) {
        int j = p0 + (i >> 2);
        int h = i & 3;
        int s = g_csr_src[j];
        float x = g_as1[s * H1 + h] + g_ad1[d * H1 + h];
        x = (x > 0.f) ? x : 0.2f * x;
        x = fmaxf(x, -60.f);
        float w = expf(x);
        g_w1c[j * H1 + h] = w;
        loc[h] += w;
    }
#pragma unroll
    for (int h = 0; h < H1; h++)
#pragma unroll
        for (int o = 16; o; o >>= 1) loc[h] += __shfl_down_sync(0xffffffffu, loc[h], o);
    __shared__ float sw[8][H1];
    if ((tid & 31) == 0)
#pragma unroll
        for (int h = 0; h < H1; h++) sw[tid >> 5][h] = loc[h];
    __syncthreads();
    __shared__ float sinv[H1];
    if (tid < H1) {
        float s = 0.f;
#pragma unroll
        for (int w = 0; w < 8; w++) s += sw[w][tid];
        sinv[tid] = 1.0f / (s + 1e-16f);
    }
    __syncthreads();

    // pass 2: fp16 gather, 2 edges in flight (threads split eo=0/1), half2 per thread
    const int eo = tid >> 7;          // which of the 2 interleaved edges
    const int fi = tid & 127;         // feature-pair index (f = 2*fi)
    const int f  = fi * 2;
    const int h  = f >> 6;
    const float inv = sinv[h];
    float2 acc = make_float2(0.f, 0.f);
    const __half2* h1h = (const __half2*)g_h1h;
    for (int j = p0 + eo; j < p1; j += 2) {
        int s = g_csr_src[j];
        float w = g_w1c[j * H1 + h];
        float2 v = __half22float2(h1h[(size_t)s * (HC / 2) + fi]);
        acc.x += w * v.x;
        acc.y += w * v.y;
    }
    __shared__ float2 part[128];
    if (eo == 1) part[fi] = acc;
    __syncthreads();
    if (eo == 0) {
        acc.x += part[fi].x;
        acc.y += part[fi].y;
        float v0 = acc.x * inv + bias1[f];
        float v1 = acc.y * inv + bias1[f + 1];
        v0 = (v0 > 0.f) ? v0 : expm1f(v0);
        v1 = (v1 > 0.f) ? v1 : expm1f(v1);
        g_x1[(size_t)d * HC + f]     = v0;
        g_x1[(size_t)d * HC + f + 1] = v1;
    }
}

// ---------------- fused edge-softmax + fp16 gather, layer 2 ----------------
__global__ __launch_bounds__(64) void gat2_k(const float* __restrict__ bias2,
                                             float* __restrict__ out) {
    const int d = blockIdx.x;
    const int tid = threadIdx.x;
    const int p0 = g_ptr[d], p1 = g_ptr[d + 1];
    const int cnt = p1 - p0;

    float loc = 0.f;
    const float ad = g_ad2[d];
    for (int i = tid; i < cnt; i += 64) {
        int j = p0 + i;
        int s = g_csr_src[j];
        float x = g_as2[s] + ad;
        x = (x > 0.f) ? x : 0.2f * x;
        x = fmaxf(x, -60.f);
        float w = expf(x);
        g_w2c[j] = w;
        loc += w;
    }
#pragma unroll
    for (int o = 16; o; o >>= 1) loc += __shfl_down_sync(0xffffffffu, loc, o);
    __shared__ float sw2[2];
    if ((tid & 31) == 0) sw2[tid >> 5] = loc;
    __syncthreads();
    __shared__ float sinv2;
    if (tid == 0) sinv2 = 1.0f / (sw2[0] + sw2[1] + 1e-16f);
    __syncthreads();

    // fp16 gather, 2 edges in flight
    const int eo = tid >> 5;          // 0 or 1
    const int fi = tid & 31;          // feature-pair index (f = 2*fi)
    const int f  = fi * 2;
    const float inv = sinv2;
    float2 acc = make_float2(0.f, 0.f);
    const __half2* h2h = (const __half2*)g_h2h;
    for (int j = p0 + eo; j < p1; j += 2) {
        int s = g_csr_src[j];
        float w = g_w2c[j];
        float2 v = __half22float2(h2h[(size_t)s * (C2 / 2) + fi]);
        acc.x += w * v.x;
        acc.y += w * v.y;
    }
    __shared__ float2 part2[32];
    if (eo == 1) part2[fi] = acc;
    __syncthreads();
    if (eo == 0) {
        acc.x += part2[fi].x;
        acc.y += part2[fi].y;
        out[(size_t)d * C2 + f]     = acc.x * inv + bias2[f];
        out[(size_t)d * C2 + f + 1] = acc.y * inv + bias2[f + 1];
    }
}

// ---------------- launch ----------------
extern "C" void kernel_launch(void* const* d_in, const int* in_sizes, int n_in,
                              void* d_out, int out_size) {
    const float* x   = (const float*)d_in[0];
    const void*  ei  = d_in[1];
    const float* W1  = (const float*)d_in[2];
    const float* as1 = (const float*)d_in[3];
    const float* ad1 = (const float*)d_in[4];
    const float* b1  = (const float*)d_in[5];
    const float* W2  = (const float*)d_in[6];
    const float* as2 = (const float*)d_in[7];
    const float* ad2 = (const float*)d_in[8];
    const float* b2  = (const float*)d_in[9];
    float* out = (float*)d_out;

    // R7 root cause: resolve true device addresses of __device__ symbols
    // used as kernel args (host-shadow writes silently absorbed via ATS).
    float  *h1p = nullptr, *x1p = nullptr, *h2p = nullptr;
    __half *h1hp = nullptr, *h2hp = nullptr;
    cudaGetSymbolAddress((void**)&h1p,  g_h1);
    cudaGetSymbolAddress((void**)&x1p,  g_x1);
    cudaGetSymbolAddress((void**)&h2p,  g_h2);
    cudaGetSymbolAddress((void**)&h1hp, g_h1h);
    cudaGetSymbolAddress((void**)&h2hp, g_h2h);

    detect_zero_k<<<(NN + 255) / 256, 256>>>((const long long*)ei);
    count_k<<<(ET + 255) / 256, 256>>>(ei);
    scan_fast_k<<<1, 1024>>>();
    scatter_k<<<(ET + 255) / 256, 256>>>(ei);

    // layer 1: h1 = x @ W1  (20000x256 @ 256x256), fp32 + fp16 copy
    { dim3 g(HC / 64, (NN + 63) / 64); sgemm_k<<<g, 256>>>(x, W1, h1p, h1hp, NN, HC, KIN); }
    att1_k<<<(NN * H1 + 255) / 256, 256>>>(as1, ad1);
    gat1_k<<<NN, 256>>>(b1);

    // layer 2: h2 = x1 @ W2  (20000x256 @ 256x64), fp32 + fp16 copy
    { dim3 g(C2 / 64, (NN + 63) / 64); sgemm_k<<<g, 256>>>(x1p, W2, h2p, h2hp, NN, C2, HC); }
    att2_k<<<(NN + 255) / 256, 256>>>(as2, ad2);
    gat2_k<<<NN, 64>>>(b2, out);
}